// round 16
// baseline (speedup 1.0000x reference)
#include <cuda_runtime.h>
#include <math.h>

// Problem constants
constexpr int B = 64;
constexpr int T = 512;
constexpr int E = 256;
constexpr int H = 512;
constexpr int K = 24;
constexpr int G = 4 * H;          // 2048
constexpr int H2 = 2 * H;         // 1024
constexpr int START_TAG = 22;
constexpr int STOP_TAG = 23;
constexpr float NEG = -10000.0f;
constexpr int M_ROWS = B * T;     // 32768

constexpr int NBLK = 128;         // persistent recurrence blocks (64 per dir)
constexpr int WKP = 36;           // ws row stride (floats)

// ------------------------- device scratch (static, no allocs) ----------------
__device__ float g_x[B * T * E];
__device__ float g_xg[2][T * G * B];          // [dir][(t*G+n)*B + b]
__device__ float g_h0[B * T * H2];
__device__ float g_h1[B * T * H2];
__device__ float g_hbuf[2][2][H * B];         // [dir][parity][k*64+b]
__device__ float g_feats[B * T * K];
__device__ unsigned g_barcnt2[2][32];         // padded: one 128B line per dir
__device__ unsigned g_bargen2[2][32];         // padded

// ------------------------- small helpers -------------------------------------
static __device__ __forceinline__ unsigned smem_u32(const void* p) {
    unsigned r;
    asm("{ .reg .u64 t; cvta.to.shared.u64 t, %1; cvt.u32.u64 %0, t; }"
        : "=r"(r) : "l"(p));
    return r;
}
static __device__ __forceinline__ void cp_async16(unsigned dst, const void* src) {
    asm volatile("cp.async.cg.shared.global [%0], [%1], 16;\n" :: "r"(dst), "l"(src));
}
static __device__ __forceinline__ void cp_commit() {
    asm volatile("cp.async.commit_group;\n" ::: "memory");
}
template <int N>
static __device__ __forceinline__ void cp_wait() {
    asm volatile("cp.async.wait_group %0;\n" :: "n"(N) : "memory");
}

// packed f32x2 helpers
static __device__ __forceinline__ unsigned long long pack2(float x, float y) {
    unsigned long long r;
    asm("mov.b64 %0, {%1, %2};" : "=l"(r) : "f"(x), "f"(y));
    return r;
}
static __device__ __forceinline__ void fma2(unsigned long long& d,
                                            unsigned long long a,
                                            unsigned long long b) {
    asm("fma.rn.f32x2 %0, %1, %2, %3;" : "=l"(d) : "l"(a), "l"(b), "l"(d));
}
static __device__ __forceinline__ float2 unpack2(unsigned long long v) {
    float2 f;
    asm("mov.b64 {%0, %1}, %2;" : "=f"(f.x), "=f"(f.y) : "l"(v));
    return f;
}

// ------------------------- embedding lookup ----------------------------------
__global__ void embed_kernel(const int* __restrict__ sentence,
                             const float* __restrict__ embed) {
    int i = blockIdx.x * blockDim.x + threadIdx.x;
    if (i >= B * T * E) return;
    int e = i % E;
    int bt = i / E;
    g_x[i] = embed[(long long)sentence[bt] * E + e];
}

// ------------------------- big GEMM: xg_t = A * W^T + bias (R13 verbatim) ----
__global__ __launch_bounds__(256)
void gemm_bias_kernel(int a_sel, const float* __restrict__ W,
                      const float* __restrict__ bias, int c_dir, int Kd) {
    const float* __restrict__ A = a_sel ? g_h0 : g_x;
    float* __restrict__ C = g_xg[c_dir];

    __shared__ float As[2][16][132];
    __shared__ float Ws[2][16][132];

    int n0 = blockIdx.x * 128;
    int m0 = blockIdx.y * 128;
    int tid = threadIdx.x;
    int tx = tid & 15;
    int ty = tid >> 4;
    int tm0 = ty * 8;
    int tn0 = tx * 8;

    int lrow0 = (tid * 2) >> 2;
    int lkc0 = (tid * 2) & 3;
    int lrow1 = (tid * 2 + 1) >> 2;
    int lkc1 = (tid * 2 + 1) & 3;

    unsigned long long acc2[8][4] = {};
    float4 ra0, ra1, rw0, rw1;

    ra0 = *(const float4*)&A[(size_t)(m0 + lrow0) * Kd + lkc0 * 4];
    ra1 = *(const float4*)&A[(size_t)(m0 + lrow1) * Kd + lkc1 * 4];
    rw0 = *(const float4*)&W[(size_t)(n0 + lrow0) * Kd + lkc0 * 4];
    rw1 = *(const float4*)&W[(size_t)(n0 + lrow1) * Kd + lkc1 * 4];
    {
        float* a0 = &As[0][lkc0 * 4][lrow0];
        a0[0 * 132] = ra0.x; a0[1 * 132] = ra0.y; a0[2 * 132] = ra0.z; a0[3 * 132] = ra0.w;
        float* a1 = &As[0][lkc1 * 4][lrow1];
        a1[0 * 132] = ra1.x; a1[1 * 132] = ra1.y; a1[2 * 132] = ra1.z; a1[3 * 132] = ra1.w;
        float* w0 = &Ws[0][lkc0 * 4][lrow0];
        w0[0 * 132] = rw0.x; w0[1 * 132] = rw0.y; w0[2 * 132] = rw0.z; w0[3 * 132] = rw0.w;
        float* w1 = &Ws[0][lkc1 * 4][lrow1];
        w1[0 * 132] = rw1.x; w1[1 * 132] = rw1.y; w1[2 * 132] = rw1.z; w1[3 * 132] = rw1.w;
    }
    __syncthreads();

    int nK = Kd / 16;
    for (int kt = 0; kt < nK; kt++) {
        int buf = kt & 1;
        if (kt + 1 < nK) {
            int k0 = (kt + 1) * 16;
            ra0 = *(const float4*)&A[(size_t)(m0 + lrow0) * Kd + k0 + lkc0 * 4];
            ra1 = *(const float4*)&A[(size_t)(m0 + lrow1) * Kd + k0 + lkc1 * 4];
            rw0 = *(const float4*)&W[(size_t)(n0 + lrow0) * Kd + k0 + lkc0 * 4];
            rw1 = *(const float4*)&W[(size_t)(n0 + lrow1) * Kd + k0 + lkc1 * 4];
        }
        #pragma unroll
        for (int k = 0; k < 16; k++) {
            float4 a0 = *(const float4*)&As[buf][k][tm0];
            float4 a1 = *(const float4*)&As[buf][k][tm0 + 4];
            ulonglong2 wA = *(const ulonglong2*)&Ws[buf][k][tn0];
            ulonglong2 wB = *(const ulonglong2*)&Ws[buf][k][tn0 + 4];
            unsigned long long wp[4] = {wA.x, wA.y, wB.x, wB.y};
            float av[8] = {a0.x, a0.y, a0.z, a0.w, a1.x, a1.y, a1.z, a1.w};
            #pragma unroll
            for (int i = 0; i < 8; i++) {
                unsigned long long ad = pack2(av[i], av[i]);
                #pragma unroll
                for (int j = 0; j < 4; j++)
                    fma2(acc2[i][j], ad, wp[j]);
            }
        }
        if (kt + 1 < nK) {
            int nbuf = buf ^ 1;
            float* a0 = &As[nbuf][lkc0 * 4][lrow0];
            a0[0 * 132] = ra0.x; a0[1 * 132] = ra0.y; a0[2 * 132] = ra0.z; a0[3 * 132] = ra0.w;
            float* a1 = &As[nbuf][lkc1 * 4][lrow1];
            a1[0 * 132] = ra1.x; a1[1 * 132] = ra1.y; a1[2 * 132] = ra1.z; a1[3 * 132] = ra1.w;
            float* w0 = &Ws[nbuf][lkc0 * 4][lrow0];
            w0[0 * 132] = rw0.x; w0[1 * 132] = rw0.y; w0[2 * 132] = rw0.z; w0[3 * 132] = rw0.w;
            float* w1 = &Ws[nbuf][lkc1 * 4][lrow1];
            w1[0 * 132] = rw1.x; w1[1 * 132] = rw1.y; w1[2 * 132] = rw1.z; w1[3 * 132] = rw1.w;
        }
        __syncthreads();
    }

    int b = m0 >> 9;
    int t0 = m0 & 511;
    #pragma unroll
    for (int i = 0; i < 8; i++) {
        int t = t0 + tm0 + i;
        #pragma unroll
        for (int j = 0; j < 4; j++) {
            float2 c = unpack2(acc2[i][j]);
            int n = n0 + tn0 + 2 * j;
            C[((size_t)t * G + n) * B + b] = c.x + bias[n];
            C[((size_t)t * G + n + 1) * B + b] = c.y + bias[n + 1];
        }
    }
}

// ------------------------- per-direction grid barrier -------------------------
// Padded counters (one 128B line each) + nanosleep backoff in the spin.
__device__ __forceinline__ void grid_barrier_dir(int dir) {
    __syncthreads();
    if (threadIdx.x == 0) {
        __threadfence();
        volatile unsigned* gv = &g_bargen2[dir][0];
        unsigned gen = *gv;
        unsigned ticket = atomicAdd(&g_barcnt2[dir][0], 1);
        if ((ticket + 1u) % 64u == 0u) {
            atomicAdd(&g_bargen2[dir][0], 1u);
        } else {
            while (*gv == gen) { __nanosleep(64); }
        }
        __threadfence();
    }
    __syncthreads();
}

// ------------------------- persistent bidirectional LSTM layer ---------------
// R13 design (gate-permuted ws, register pointwise, 2x256k chunks) with the
// xg prefetch software-pipelined to overlap the barrier wait.
__global__ __launch_bounds__(256, 1)
void lstm_layer_kernel(const float* __restrict__ whh_f,
                       const float* __restrict__ whh_b, int layer) {
    extern __shared__ float sm[];
    float* ws = sm;                         // [512][WKP]
    float* hs = ws + 512 * WKP;             // [2][256*64]

    int tid = threadIdx.x;
    int bx = blockIdx.x;
    int dir = bx >> 6;
    int h0 = (bx & 63) * 8;
    const float* __restrict__ Wm = dir ? whh_b : whh_f;
    const float* __restrict__ xg = g_xg[dir];
    float* __restrict__ hout = layer ? g_h1 : g_h0;

    int lane = tid & 31;        // b0 = lane*2
    int ty = tid >> 5;          // hidx = ty (0..7)
    int b0 = lane * 2;
    int q0 = ty * 4;            // ws column base: 4 gates of hidx=ty

    unsigned hs_u32 = smem_u32(hs);

    // ---- load + transpose weights into SMEM, gate-permuted (once) ----
    {
        int r = tid >> 3;                   // 0..31  (gate*8 + hidx)
        int gate = r >> 3;
        int hidx = r & 7;
        int q = hidx * 4 + gate;
        int n = gate * H + h0 + hidx;
        const float* wrow = &Wm[(size_t)n * H];
        #pragma unroll
        for (int it = 0; it < 16; it++) {
            int kc4 = (tid & 7) + it * 8;   // float4 idx 0..127
            float4 w = *(const float4*)&wrow[kc4 * 4];
            float* d = &ws[(kc4 * 4) * WKP + q];
            d[0 * WKP] = w.x; d[1 * WKP] = w.y; d[2 * WKP] = w.z; d[3 * WKP] = w.w;
        }
    }

    // zero parity-0 h slice
    {
        float* z = g_hbuf[dir][0];
        for (int i = tid; i < 8 * 64; i += 256) z[h0 * 64 + i] = 0.0f;
    }
    float c_reg0 = 0.0f, c_reg1 = 0.0f;     // c for (hidx=ty, b0), (ty, b0+1)

    // prefetch xg for step 0 (overlaps the initial barrier)
    float2 xv[4];
    {
        int t0i = dir ? (T - 1) : 0;
        #pragma unroll
        for (int g = 0; g < 4; g++)
            xv[g] = __ldg((const float2*)&xg[((size_t)t0i * G + g * H + h0 + ty) * B + b0]);
    }
    grid_barrier_dir(dir);

    for (int s = 0; s < T; s++) {
        int p = s & 1;
        int t = dir ? (T - 1 - s) : s;
        const float* __restrict__ hcur = g_hbuf[dir][p];
        float* __restrict__ hnext = g_hbuf[dir][p ^ 1];

        // chunk 0 (k 0..255) into buf0, chunk 1 into buf1 (pipelined)
        #pragma unroll
        for (int j = 0; j < 16; j++) {
            int f4 = tid + j * 256;         // 0..4095 float4s
            cp_async16(hs_u32 + f4 * 16, &hcur[f4 * 4]);
        }
        cp_commit();
        #pragma unroll
        for (int j = 0; j < 16; j++) {
            int f4 = tid + j * 256;
            cp_async16(hs_u32 + (16384 + f4 * 4) * 4, &hcur[16384 + f4 * 4]);
        }
        cp_commit();

        unsigned long long acc2[2][2] = {}; // [gate-pair][b]

        #pragma unroll
        for (int c = 0; c < 2; c++) {
            if (c == 0) { cp_wait<1>(); } else { cp_wait<0>(); }
            __syncthreads();

            const float* hb = &hs[c * 16384];
            const float* wb = &ws[(c * 256) * WKP];
            #pragma unroll 4
            for (int k = 0; k < 256; k++) {
                ulonglong2 w2 = *(const ulonglong2*)&wb[k * WKP + q0];
                float2 h = *(const float2*)&hb[k * 64 + b0];
                unsigned long long hx = pack2(h.x, h.x);
                unsigned long long hy = pack2(h.y, h.y);
                fma2(acc2[0][0], w2.x, hx);   // gates (i,f) @ b0
                fma2(acc2[0][1], w2.x, hy);   // gates (i,f) @ b0+1
                fma2(acc2[1][0], w2.y, hx);   // gates (g,o) @ b0
                fma2(acc2[1][1], w2.y, hy);   // gates (g,o) @ b0+1
            }
        }

        // pointwise LSTM in registers
        float2 u00 = unpack2(acc2[0][0]);   // (i, f) @ b0
        float2 u10 = unpack2(acc2[1][0]);   // (g, o) @ b0
        float2 u01 = unpack2(acc2[0][1]);   // (i, f) @ b0+1
        float2 u11 = unpack2(acc2[1][1]);   // (g, o) @ b0+1

        float gi0 = u00.x + xv[0].x, gf0 = u00.y + xv[1].x;
        float gc0 = u10.x + xv[2].x, go0 = u10.y + xv[3].x;
        float gi1 = u01.x + xv[0].y, gf1 = u01.y + xv[1].y;
        float gc1 = u11.x + xv[2].y, go1 = u11.y + xv[3].y;

        float si0 = 1.0f / (1.0f + expf(-gi0));
        float sf0 = 1.0f / (1.0f + expf(-gf0));
        float so0 = 1.0f / (1.0f + expf(-go0));
        float si1 = 1.0f / (1.0f + expf(-gi1));
        float sf1 = 1.0f / (1.0f + expf(-gf1));
        float so1 = 1.0f / (1.0f + expf(-go1));

        c_reg0 = sf0 * c_reg0 + si0 * tanhf(gc0);
        c_reg1 = sf1 * c_reg1 + si1 * tanhf(gc1);
        float hn0 = so0 * tanhf(c_reg0);
        float hn1 = so1 * tanhf(c_reg1);

        *(float2*)&hnext[(h0 + ty) * 64 + b0] = make_float2(hn0, hn1);
        size_t ob = ((size_t)b0 * T + t) * H2 + dir * H + h0 + ty;
        hout[ob] = hn0;
        hout[ob + (size_t)T * H2] = hn1;    // b0+1

        // prefetch next step's xg BEFORE the barrier (overlaps the wait)
        if (s + 1 < T) {
            int tn = dir ? (T - 2 - s) : (s + 1);
            #pragma unroll
            for (int g = 0; g < 4; g++)
                xv[g] = __ldg((const float2*)&xg[((size_t)tn * G + g * H + h0 + ty) * B + b0]);
        }

        grid_barrier_dir(dir);
    }
}

// ------------------------- output projection (K=24) --------------------------
__global__ __launch_bounds__(256)
void proj_kernel(const float* __restrict__ w_out, const float* __restrict__ b_out) {
    int bt = blockIdx.x;
    int wid = threadIdx.x >> 5;
    int lane = threadIdx.x & 31;
    const float* hrow = g_h1 + (long long)bt * H2;

    for (int j = wid; j < K; j += 8) {
        const float* wr = w_out + j * H2;
        float s = 0.0f;
        for (int k = lane; k < H2; k += 32)
            s += hrow[k] * wr[k];
        #pragma unroll
        for (int off = 16; off; off >>= 1)
            s += __shfl_xor_sync(0xffffffff, s, off);
        if (lane == 0)
            g_feats[bt * K + j] = s + b_out[j];
    }
}

// ------------------------- Viterbi decode ------------------------------------
__global__ void viterbi_kernel(const float* __restrict__ trans,
                               float* __restrict__ out, int out_size) {
    int b = blockIdx.x;
    int tid = threadIdx.x;

    __shared__ float tr[K][K];
    __shared__ float v[K];
    __shared__ float vn[K];
    __shared__ unsigned char bp[T][K];

    for (int i = tid; i < K * K; i += 32)
        tr[i / K][i % K] = trans[i];
    if (tid < K)
        v[tid] = (tid == START_TAG) ? 0.0f : NEG;
    __syncthreads();

    for (int t = 0; t < T; t++) {
        if (tid < K) {
            float best = -3.4e38f;
            int arg = 0;
            #pragma unroll
            for (int kp = 0; kp < K; kp++) {
                float sc = v[kp] + tr[tid][kp];
                if (sc > best) { best = sc; arg = kp; }
            }
            vn[tid] = best + g_feats[(b * T + t) * K + tid];
            bp[t][tid] = (unsigned char)arg;
        }
        __syncthreads();
        if (tid < K) v[tid] = vn[tid];
        __syncthreads();
    }

    if (tid == 0) {
        float best = -3.4e38f;
        int arg = 0;
        for (int k = 0; k < K; k++) {
            float sc = v[k] + tr[STOP_TAG][k];
            if (sc > best) { best = sc; arg = k; }
        }
        if (out_size >= B + B * T) {
            out[b] = best;
            int tag = arg;
            for (int t = T - 1; t >= 0; t--) {
                out[B + b * T + t] = (float)tag;
                tag = bp[t][tag];
            }
        } else if (out_size >= B * T) {
            int tag = arg;
            for (int t = T - 1; t >= 0; t--) {
                out[b * T + t] = (float)tag;
                tag = bp[t][tag];
            }
        } else {
            out[b] = best;
        }
    }
}

// ------------------------- launch --------------------------------------------
extern "C" void kernel_launch(void* const* d_in, const int* in_sizes, int n_in,
                              void* d_out, int out_size) {
    const int*   sentence = (const int*)d_in[0];
    const float* embed    = (const float*)d_in[1];
    const float* w_ih_l0f = (const float*)d_in[2];
    const float* w_hh_l0f = (const float*)d_in[3];
    const float* b_l0f    = (const float*)d_in[4];
    const float* w_ih_l0b = (const float*)d_in[5];
    const float* w_hh_l0b = (const float*)d_in[6];
    const float* b_l0b    = (const float*)d_in[7];
    const float* w_ih_l1f = (const float*)d_in[8];
    const float* w_hh_l1f = (const float*)d_in[9];
    const float* b_l1f    = (const float*)d_in[10];
    const float* w_ih_l1b = (const float*)d_in[11];
    const float* w_hh_l1b = (const float*)d_in[12];
    const float* b_l1b    = (const float*)d_in[13];
    const float* w_out    = (const float*)d_in[14];
    const float* b_out    = (const float*)d_in[15];
    const float* trans    = (const float*)d_in[16];
    float* out = (float*)d_out;

    const int lstm_smem = (512 * WKP + 2 * 256 * 64) * 4;   // 204800 B
    cudaFuncSetAttribute(lstm_layer_kernel,
                         cudaFuncAttributeMaxDynamicSharedMemorySize, lstm_smem);

    // 1. embedding
    embed_kernel<<<(B * T * E + 255) / 256, 256>>>(sentence, embed);

    // 2. layer-0 input-gate GEMMs (Kd=256)
    dim3 ggrid(G / 128, M_ROWS / 128);
    gemm_bias_kernel<<<ggrid, 256>>>(0, w_ih_l0f, b_l0f, 0, E);
    gemm_bias_kernel<<<ggrid, 256>>>(0, w_ih_l0b, b_l0b, 1, E);

    // 3. layer-0 recurrence (persistent)
    lstm_layer_kernel<<<NBLK, 256, lstm_smem>>>(w_hh_l0f, w_hh_l0b, 0);

    // 4. layer-1 input-gate GEMMs (Kd=1024)
    gemm_bias_kernel<<<ggrid, 256>>>(1, w_ih_l1f, b_l1f, 0, H2);
    gemm_bias_kernel<<<ggrid, 256>>>(1, w_ih_l1b, b_l1b, 1, H2);

    // 5. layer-1 recurrence
    lstm_layer_kernel<<<NBLK, 256, lstm_smem>>>(w_hh_l1f, w_hh_l1b, 1);

    // 6. emission features
    proj_kernel<<<B * T, 256>>>(w_out, b_out);

    // 7. Viterbi decode + output
    viterbi_kernel<<<B, 32>>>(trans, out, out_size);
}